// round 2
// baseline (speedup 1.0000x reference)
#include <cuda_runtime.h>
#include <math.h>
#include <stdint.h>

#define CIN 48
#define CB  8
#define H   4096
#define HV  (H/4)            // float4 per full channel row
#define NTHREADS 512
#define NWARPS   (NTHREADS/32)   // 16
#define NPAIR    36              // upper-triangle incl. diag of 8x8
#define SCALE    0.35355339059327373f   // 1/sqrt(8)

__device__ __forceinline__ uint32_t smem_u32(const void* p) {
    uint32_t a;
    asm("{ .reg .u64 t; cvta.to.shared.u64 t, %1; cvt.u32.u64 %0, t; }"
        : "=r"(a) : "l"(p));
    return a;
}

__device__ __forceinline__ uint32_t my_cluster_rank() {
    uint32_t r;
    asm("mov.u32 %0, %%cluster_ctarank;" : "=r"(r));
    return r;
}

__device__ __forceinline__ float ld_dsmem_f32(uint32_t local_addr, uint32_t rank) {
    uint32_t raddr;
    float v;
    asm("mapa.shared::cluster.u32 %0, %1, %2;" : "=r"(raddr) : "r"(local_addr), "r"(rank));
    asm volatile("ld.shared::cluster.f32 %0, [%1];" : "=f"(v) : "r"(raddr));
    return v;
}

__global__ __launch_bounds__(NTHREADS, 2) __cluster_dims__(2, 1, 1)
void ultimus_kernel(const float* __restrict__ x,
                    const float* __restrict__ wd,   // [8,48]
                    const float* __restrict__ wu,   // [48,8]
                    float* __restrict__ out)
{
    __shared__ float s_wd[CB * CIN];          // 384
    __shared__ float s_gpart[NWARPS * NPAIR]; // 16*36
    __shared__ float s_G36[NPAIR];            // this half's upper-tri gram
    __shared__ float s_G[CB * CB];            // full gram (both halves)
    __shared__ float s_AM[CB * CB];
    __shared__ float s_W2[CIN * CB];          // W2 = w_up @ am

    const int b    = blockIdx.x >> 1;
    const int half = blockIdx.x & 1;
    const int t    = threadIdx.x;
    const int lane = t & 31;
    const int warp = t >> 5;
    const uint32_t rank = my_cluster_rank();

    if (t < CB * CIN) s_wd[t] = wd[t];
    __syncthreads();

    // ---------------- Pass 1: kqv = w_down @ x, kept in registers ----------
    const float4* __restrict__ x4 = (const float4*)(x + (size_t)b * CIN * H);
    const int hoff = half * (NTHREADS) + t;   // float4 index within row (H/2 chunk = 512 f4)

    float acc[CB][4];
    #pragma unroll
    for (int o = 0; o < CB; o++) {
        acc[o][0] = 0.f; acc[o][1] = 0.f; acc[o][2] = 0.f; acc[o][3] = 0.f;
    }

    #pragma unroll 4
    for (int c = 0; c < CIN; c++) {
        float4 xv = __ldcs(&x4[c * HV + hoff]);
        #pragma unroll
        for (int o = 0; o < CB; o++) {
            float w = s_wd[o * CIN + c];
            acc[o][0] += w * xv.x;
            acc[o][1] += w * xv.y;
            acc[o][2] += w * xv.z;
            acc[o][3] += w * xv.w;
        }
    }

    // ---------------- Gram partials over this half ---------------------------
    {
        int base = 0;
        #pragma unroll
        for (int i = 0; i < CB; i++) {
            #pragma unroll
            for (int j = i; j < CB; j++) {
                float s = acc[i][0] * acc[j][0] + acc[i][1] * acc[j][1]
                        + acc[i][2] * acc[j][2] + acc[i][3] * acc[j][3];
                #pragma unroll
                for (int off = 16; off > 0; off >>= 1)
                    s += __shfl_xor_sync(0xffffffffu, s, off);
                if (lane == 0) s_gpart[warp * NPAIR + base] = s;
                base++;
            }
        }
    }
    __syncthreads();

    if (t < NPAIR) {
        float s = 0.f;
        #pragma unroll
        for (int w = 0; w < NWARPS; w++) s += s_gpart[w * NPAIR + t];
        s_G36[t] = s;
    }
    __syncthreads();

    // ---------------- Cluster exchange: add peer half's gram ----------------
    asm volatile("barrier.cluster.arrive.aligned;" ::: "memory");
    asm volatile("barrier.cluster.wait.aligned;" ::: "memory");

    if (t < NPAIR) {
        uint32_t myaddr = smem_u32(&s_G36[t]);
        float peer = ld_dsmem_f32(myaddr, rank ^ 1u);
        float s = s_G36[t] + peer;
        // linear upper-tri index -> (i, j)
        int i = 0, rem = t;
        while (rem >= CB - i) { rem -= CB - i; i++; }
        int j = i + rem;
        s_G[i * CB + j] = s;
        s_G[j * CB + i] = s;
    }
    __syncthreads();

    // ---------------- Softmax rows of G*SCALE -> AM --------------------------
    if (t < CB) {
        float v[CB];
        float m = -1e30f;
        #pragma unroll
        for (int j = 0; j < CB; j++) {
            v[j] = s_G[t * CB + j] * SCALE;
            m = fmaxf(m, v[j]);
        }
        float sum = 0.f;
        #pragma unroll
        for (int j = 0; j < CB; j++) {
            v[j] = __expf(v[j] - m);
            sum += v[j];
        }
        float inv = 1.f / sum;
        #pragma unroll
        for (int j = 0; j < CB; j++) s_AM[t * CB + j] = v[j] * inv;
    }
    __syncthreads();

    // ---------------- W2[c][j] = sum_o wu[c][o] * AM[o][j] -------------------
    if (t < CIN * CB) {
        int c = t >> 3, j = t & 7;
        float s = 0.f;
        #pragma unroll
        for (int o = 0; o < CB; o++) s += wu[c * CB + o] * s_AM[o * CB + j];
        s_W2[c * CB + j] = s;
    }
    __syncthreads();

    // ---------------- Pass 2: out[c][h] = sum_j W2[c][j] * kqv[j][h] ---------
    float4* __restrict__ out4 = (float4*)(out + (size_t)b * CIN * H);

    #pragma unroll 4
    for (int c = 0; c < CIN; c++) {
        const float4 w0 = ((const float4*)(s_W2 + c * CB))[0];
        const float4 w1 = ((const float4*)(s_W2 + c * CB))[1];
        float4 r;
        r.x = w0.x * acc[0][0] + w0.y * acc[1][0] + w0.z * acc[2][0] + w0.w * acc[3][0]
            + w1.x * acc[4][0] + w1.y * acc[5][0] + w1.z * acc[6][0] + w1.w * acc[7][0];
        r.y = w0.x * acc[0][1] + w0.y * acc[1][1] + w0.z * acc[2][1] + w0.w * acc[3][1]
            + w1.x * acc[4][1] + w1.y * acc[5][1] + w1.z * acc[6][1] + w1.w * acc[7][1];
        r.z = w0.x * acc[0][2] + w0.y * acc[1][2] + w0.z * acc[2][2] + w0.w * acc[3][2]
            + w1.x * acc[4][2] + w1.y * acc[5][2] + w1.z * acc[6][2] + w1.w * acc[7][2];
        r.w = w0.x * acc[0][3] + w0.y * acc[1][3] + w0.z * acc[2][3] + w0.w * acc[3][3]
            + w1.x * acc[4][3] + w1.y * acc[5][3] + w1.z * acc[6][3] + w1.w * acc[7][3];
        __stwt(&out4[c * HV + hoff], r);
    }

    // keep this CTA's smem alive until the peer has read s_G36
    asm volatile("barrier.cluster.arrive.aligned;" ::: "memory");
    asm volatile("barrier.cluster.wait.aligned;" ::: "memory");
}

extern "C" void kernel_launch(void* const* d_in, const int* in_sizes, int n_in,
                              void* d_out, int out_size)
{
    const float* x  = (const float*)d_in[0];   // [256, 48, 4096, 1]
    const float* wd = (const float*)d_in[1];   // [8, 48]
    const float* wu = (const float*)d_in[2];   // [48, 8]
    float* out = (float*)d_out;                // [256, 48, 4096, 1]

    ultimus_kernel<<<512, NTHREADS>>>(x, wd, wu, out);
}